// round 12
// baseline (speedup 1.0000x reference)
#include <cuda_runtime.h>
#include <cuda_bf16.h>

// out shape: (B=8, C=256, H=128, W=128) fp32, row-major. Output is independent
// of the input tensor and identical across batches:
//   out[b,c,i,j] = c<128 ? trig_c(i) : trig_{c-128}(j)
//   trig_cc(p)   = (cc even ? sin : cos)(p * 10000^(-floor(cc/2)/128))
//
// Write-injection at the SM->LTS fabric write cap (6.7-6.9 TB/s measured over
// six holds with the STG.128 variant). This round's experiment: sm_103a
// 256-bit stores (st.global.cs.v8.f32 -> STG.256) — halves store instruction
// count, doubling bytes per LSU dispatch slot. Tests whether any of the
// residual 3-4% below nominal cap is LSU-dispatch-side. Scheduling shape is
// unchanged from the proven config: one block per (b,c) plane, 2048 blocks,
// register-staged back-to-back streaming bursts.

__global__ __launch_bounds__(256) void pe2d_kernel(float* __restrict__ out) {
    const int bc  = blockIdx.x;       // b*256 + c
    const int c   = bc & 255;
    const int tid = threadIdx.x;

    __shared__ float s[128];

    if (tid < 128) {
        const int cc    = c & 127;        // channel within half
        const int pairk = cc >> 1;        // floor(cc/2)
        const float LOG2_10000 = 13.28771237954945f;
        float inv_dim = exp2f(-(float)pairk * (LOG2_10000 / 128.0f));
        float arg = (float)tid * inv_dim; // tid = position (i or j)
        float sv, cv;
        sincosf(arg, &sv, &cv);
        s[tid] = (cc & 1) ? cv : sv;
    }
    __syncthreads();

    // Plane = 2048 x 32B units; 256 threads -> 8 units each. Consecutive
    // lanes write consecutive 32B (1KB per warp per store, fully coalesced).
    // Stage all 64 payload floats in registers, then burst 8 STG.256.cs.
    float v[8][8];
    if (c < 128) {
        // value constant along j: unit's row = idx8 >> 4 (16 units per row)
        #pragma unroll
        for (int t = 0; t < 8; t++) {
            const int row = (tid + t * 256) >> 4;   // warp-uniform
            const float x = s[row];                 // smem broadcast
            #pragma unroll
            for (int k = 0; k < 8; k++) v[t][k] = x;
        }
    } else {
        // value varies along j only: unit covers cols [(idx8&15)*8, +8)
        #pragma unroll
        for (int t = 0; t < 8; t++) {
            const int j0 = ((tid + t * 256) & 15) * 8;
            #pragma unroll
            for (int k = 0; k < 8; k++) v[t][k] = s[j0 + k];  // conflict-free
        }
    }

    float* base = out + (size_t)bc * 16384 + (size_t)tid * 8;
    #pragma unroll
    for (int t = 0; t < 8; t++) {
        float* p = base + (size_t)t * 2048;         // 256 threads * 8 floats
        asm volatile(
            "st.global.cs.v8.f32 [%0], {%1, %2, %3, %4, %5, %6, %7, %8};"
            :: "l"(p),
               "f"(v[t][0]), "f"(v[t][1]), "f"(v[t][2]), "f"(v[t][3]),
               "f"(v[t][4]), "f"(v[t][5]), "f"(v[t][6]), "f"(v[t][7])
            : "memory");
    }
}

extern "C" void kernel_launch(void* const* d_in, const int* in_sizes, int n_in,
                              void* d_out, int out_size) {
    (void)d_in; (void)in_sizes; (void)n_in; (void)out_size;
    // 8 batches * 256 channels = 2048 planes
    pe2d_kernel<<<2048, 256>>>((float*)d_out);
}